// round 6
// baseline (speedup 1.0000x reference)
#include <cuda_runtime.h>

// Shapes fixed for this problem: B=64, C=2, H=W=512.
#define HW_SHIFT 18
#define HW (1 << HW_SHIFT)
#define KMAX 1000
#define NBUCK 1024                  // coarse buckets = top 10 bits of float pattern
#define CAP (1 << 21)               // candidate buffer per channel
#define GRID2 444
#define BLK2 512

// ---------------- device scratch (zero-init at load; reset per-invocation by
// the last-block epilogues, so replays are deterministic) ------------------
__device__ double   g_pos_sum[2];
__device__ int      g_num_pos[2];
__device__ unsigned g_shist[2][NBUCK];
__device__ int      g_bcut[2];
__device__ int      g_cand_cnt[2];
__device__ float    g_cand[2][CAP];
__device__ unsigned g_done1;
__device__ unsigned g_done2;

// =====================  K1: sampled histogram + bcut  =====================
// Samples 1/64 of elements (32-contiguous chunks every 2048 -> coalesced).
// Last block: suffix-scan the histogram, pick largest bucket with >=64
// sampled values above it (=> ~4096+ true candidates >> KMAX w.h.p.),
// then zero all accumulators for K2 / the next replay.
__global__ void __launch_bounds__(1024) k_sample(
    const float* __restrict__ outp, const float* __restrict__ cm,
    const float* __restrict__ am, int N) {
  __shared__ unsigned hc[NBUCK], ha[NBUCK];
  __shared__ unsigned ss[NBUCK];
  __shared__ unsigned sh_last;
  __shared__ int sh_b;
  int tid = threadIdx.x;
  for (int i = tid; i < NBUCK; i += 1024) { hc[i] = 0u; ha[i] = 0u; }
  __syncthreads();
  int j = blockIdx.x * 1024 + tid;                 // sample index
  int i = ((j >> 5) << 11) + (j & 31);             // element index
  if (i < N) {
    int b = i >> HW_SHIFT, s = i & (HW - 1);
    size_t base = ((size_t)b) << (HW_SHIFT + 1);
    float pc = outp[base + s], pa = outp[base + HW + s];
    if (cm[i] == 0.0f) { float v = pc * pc; atomicAdd(&hc[__float_as_uint(v) >> 22], 1u); }
    if (am[i] == 0.0f) { float v = pa * pa; atomicAdd(&ha[__float_as_uint(v) >> 22], 1u); }
  }
  __syncthreads();
  for (int q = tid; q < NBUCK; q += 1024) {
    if (hc[q]) atomicAdd(&g_shist[0][q], hc[q]);
    if (ha[q]) atomicAdd(&g_shist[1][q], ha[q]);
  }
  __threadfence();
  __syncthreads();
  if (tid == 0) sh_last = atomicAdd(&g_done1, 1u);
  __syncthreads();
  if (sh_last != gridDim.x - 1) return;

  // ---- last block only ----
  for (int ch = 0; ch < 2; ch++) {
    ss[tid] = __ldcg(&g_shist[ch][tid]);
    __syncthreads();
    for (int off = 1; off < 1024; off <<= 1) {     // suffix (from-top) scan
      unsigned v = (tid + off < 1024) ? ss[tid + off] : 0u;
      __syncthreads();
      ss[tid] += v;
      __syncthreads();
    }
    if (tid == 0) sh_b = 0;
    __syncthreads();
    unsigned here = ss[tid];
    unsigned nxt = (tid < 1023) ? ss[tid + 1] : 0u;
    if (here >= 64u && nxt < 64u) sh_b = tid;      // unique (monotone suffix)
    __syncthreads();
    if (tid == 0) g_bcut[ch] = sh_b;
    g_shist[ch][tid] = 0u;                         // reset for next replay
    __syncthreads();
  }
  if (tid < 2) { g_pos_sum[tid] = 0.0; g_num_pos[tid] = 0; g_cand_cnt[tid] = 0; }
  if (tid == 0) g_done1 = 0u;
}

// ------------- exact boundary finder over a shared histogram -------------
// (512-thread version). cnt/fsum[M] built. Finds bucket t with
// sum(cnt[b>t]) < need <= +cnt[t]; adds sum(fsum[b>t]) into *sh_acc.
template <int M>
__device__ __forceinline__ void find_boundary(unsigned* cnt, float* fsum, unsigned* ss,
                                              int need, int tid,
                                              int* sh_t, int* sh_rem, double* sh_acc) {
  constexpr int CH = M / 512;
  unsigned csum = 0;
#pragma unroll
  for (int q = 0; q < CH; q++) csum += cnt[tid * CH + q];
  ss[tid] = csum;
  __syncthreads();
  for (int off = 1; off < 512; off <<= 1) {
    unsigned v = (tid + off < 512) ? ss[tid + off] : 0u;
    __syncthreads();
    ss[tid] += v;
    __syncthreads();
  }
  if (tid == 0) { *sh_t = -1; *sh_rem = 0; }
  __syncthreads();
  unsigned Tj = ss[tid];
  unsigned Tj1 = (tid < 511) ? ss[tid + 1] : 0u;
  if ((int)Tj1 < need && need <= (int)Tj) {        // exactly one thread
    int r = need - (int)Tj1;
#pragma unroll
    for (int q = CH - 1; q >= 0; q--) {
      unsigned c = cnt[tid * CH + q];
      if ((int)c < r) r -= (int)c;
      else { *sh_t = tid * CH + q; *sh_rem = r; break; }
    }
  }
  __syncthreads();
  int t = *sh_t;
  double part = 0.0;
  for (int bb = tid; bb < M; bb += 512)
    if (bb > t) part += (double)fsum[bb];
  for (int o = 16; o; o >>= 1) part += __shfl_down_sync(0xffffffffu, part, o);
  if ((tid & 31) == 0 && part != 0.0) atomicAdd(sh_acc, part);
  __syncthreads();
}

// =============  K2: full float4 scan + last-block exact select  ===========
__global__ void __launch_bounds__(BLK2, 3) k_main(
    const float* __restrict__ outp, const float* __restrict__ cm,
    const float* __restrict__ am, const float* __restrict__ cw,
    const float* __restrict__ aw, float* __restrict__ dout, int N) {
  const unsigned bc0 = (unsigned)g_bcut[0];
  const unsigned bc1 = (unsigned)g_bcut[1];
  float psC = 0.f, psA = 0.f;
  int npC = 0, npA = 0;
  const int n4 = N >> 2;
  const int stride = gridDim.x * BLK2;

#define DO_ELEM(p, t, w, bc, CHN, ps, np)                                  \
  do {                                                                     \
    if ((t) != 0.0f) { float l = (p) - (t); l *= l; (ps) += l * (w); (np)++; } \
    else {                                                                 \
      float v = (p) * (p);                                                 \
      if ((__float_as_uint(v) >> 22) >= (bc)) {                            \
        int idx = atomicAdd(&g_cand_cnt[CHN], 1);                          \
        if (idx < CAP) g_cand[CHN][idx] = v;                               \
      }                                                                    \
    }                                                                      \
  } while (0)

  for (int g = blockIdx.x * BLK2 + threadIdx.x; g < n4; g += stride) {
    int i = g << 2;
    int s = i & (HW - 1);
    size_t base = ((size_t)(i >> HW_SHIFT)) << (HW_SHIFT + 1);
    float4 tc = __ldcs((const float4*)(cm + i));
    float4 ta = __ldcs((const float4*)(am + i));
    float4 pc = __ldcs((const float4*)(outp + base + s));
    float4 pa = __ldcs((const float4*)(outp + base + HW + s));
    float4 wc = make_float4(0.f, 0.f, 0.f, 0.f);
    float4 wa = make_float4(0.f, 0.f, 0.f, 0.f);
    if ((tc.x != 0.f) || (tc.y != 0.f) || (tc.z != 0.f) || (tc.w != 0.f))
      wc = __ldcs((const float4*)(cw + i));
    if ((ta.x != 0.f) || (ta.y != 0.f) || (ta.z != 0.f) || (ta.w != 0.f))
      wa = __ldcs((const float4*)(aw + i));
    DO_ELEM(pc.x, tc.x, wc.x, bc0, 0, psC, npC);
    DO_ELEM(pc.y, tc.y, wc.y, bc0, 0, psC, npC);
    DO_ELEM(pc.z, tc.z, wc.z, bc0, 0, psC, npC);
    DO_ELEM(pc.w, tc.w, wc.w, bc0, 0, psC, npC);
    DO_ELEM(pa.x, ta.x, wa.x, bc1, 1, psA, npA);
    DO_ELEM(pa.y, ta.y, wa.y, bc1, 1, psA, npA);
    DO_ELEM(pa.z, ta.z, wa.z, bc1, 1, psA, npA);
    DO_ELEM(pa.w, ta.w, wa.w, bc1, 1, psA, npA);
  }
  // scalar tail (N % 4 == 0 for this shape; executes 0 iters, kept for safety)
  if (blockIdx.x == 0 && threadIdx.x == 0) {
    for (int i = n4 << 2; i < N; i++) {
      int s = i & (HW - 1);
      size_t base = ((size_t)(i >> HW_SHIFT)) << (HW_SHIFT + 1);
      float pcx = outp[base + s], pax = outp[base + HW + s];
      float tcx = cm[i], tax = am[i];
      float wcx = (tcx != 0.f) ? cw[i] : 0.f;
      float wax = (tax != 0.f) ? aw[i] : 0.f;
      DO_ELEM(pcx, tcx, wcx, bc0, 0, psC, npC);
      DO_ELEM(pax, tax, wax, bc1, 1, psA, npA);
    }
  }
#undef DO_ELEM

  for (int o = 16; o; o >>= 1) {
    psC += __shfl_down_sync(0xffffffffu, psC, o);
    psA += __shfl_down_sync(0xffffffffu, psA, o);
    npC += __shfl_down_sync(0xffffffffu, npC, o);
    npA += __shfl_down_sync(0xffffffffu, npA, o);
  }
  if ((threadIdx.x & 31) == 0) {
    atomicAdd(&g_pos_sum[0], (double)psC);
    atomicAdd(&g_pos_sum[1], (double)psA);
    atomicAdd(&g_num_pos[0], npC);
    atomicAdd(&g_num_pos[1], npA);
  }

  // -------- last-block ticket --------
  __threadfence();
  __syncthreads();
  __shared__ unsigned sh_last;
  if (threadIdx.x == 0) sh_last = atomicAdd(&g_done2, 1u);
  __syncthreads();
  if (sh_last != gridDim.x - 1) return;

  // -------- exact top-k select (both channels), final loss --------
  __shared__ unsigned cnt[2048];
  __shared__ float fsum[2048];
  __shared__ unsigned ssb[512];
  __shared__ int sh_t, sh_rem;
  __shared__ double sh_acc;
  int tid = threadIdx.x;
  double loss_total = 0.0;

  for (int ch = 0; ch < 2; ch++) {
    int n = __ldcg(&g_cand_cnt[ch]); if (n > CAP) n = CAP;
    int np = __ldcg(&g_num_pos[ch]);
    long long nn = (long long)N - np;
    long long kk = 4LL * (long long)np;
    if (kk > KMAX) kk = KMAX;
    if (kk > nn) kk = nn;
    if (kk < 0) kk = 0;
    int k = (int)kk;
    if (tid == 0) sh_acc = 0.0;
    __syncthreads();

    int t0 = -1, t1 = -1;
    int need = k;
    if (need > 0) {                                 // level 0: bits [31:22]
      for (int i2 = tid; i2 < 1024; i2 += 512) { cnt[i2] = 0u; fsum[i2] = 0.f; }
      __syncthreads();
      for (int i2 = tid; i2 < n; i2 += 512) {
        float v = __ldcg(&g_cand[ch][i2]);
        unsigned b = __float_as_uint(v) >> 22;
        atomicAdd(&cnt[b], 1u); atomicAdd(&fsum[b], v);
      }
      __syncthreads();
      find_boundary<1024>(cnt, fsum, ssb, need, tid, &sh_t, &sh_rem, &sh_acc);
      t0 = sh_t; need = sh_rem;
    }
    if (need > 0 && t0 >= 0) {                      // level 1: bits [21:11]
      for (int i2 = tid; i2 < 2048; i2 += 512) { cnt[i2] = 0u; fsum[i2] = 0.f; }
      __syncthreads();
      for (int i2 = tid; i2 < n; i2 += 512) {
        float v = __ldcg(&g_cand[ch][i2]);
        unsigned u = __float_as_uint(v);
        if ((int)(u >> 22) == t0) {
          unsigned b = (u >> 11) & 2047u;
          atomicAdd(&cnt[b], 1u); atomicAdd(&fsum[b], v);
        }
      }
      __syncthreads();
      find_boundary<2048>(cnt, fsum, ssb, need, tid, &sh_t, &sh_rem, &sh_acc);
      t1 = sh_t; need = sh_rem;
    }
    if (need > 0 && t1 >= 0) {                      // level 2: bits [10:0]
      for (int i2 = tid; i2 < 2048; i2 += 512) { cnt[i2] = 0u; fsum[i2] = 0.f; }
      __syncthreads();
      for (int i2 = tid; i2 < n; i2 += 512) {
        float v = __ldcg(&g_cand[ch][i2]);
        unsigned u = __float_as_uint(v);
        if ((int)(u >> 22) == t0 && (int)((u >> 11) & 2047u) == t1) {
          unsigned b = u & 2047u;
          atomicAdd(&cnt[b], 1u); atomicAdd(&fsum[b], v);
        }
      }
      __syncthreads();
      find_boundary<2048>(cnt, fsum, ssb, need, tid, &sh_t, &sh_rem, &sh_acc);
      if (tid == 0 && sh_t >= 0 && sh_rem > 0) {
        // all 32 bits fixed -> identical values; take rem copies exactly
        float v = __uint_as_float(((unsigned)t0 << 22) | ((unsigned)t1 << 11) | (unsigned)sh_t);
        atomicAdd(&sh_acc, (double)sh_rem * (double)v);
      }
      __syncthreads();
    }

    if (tid == 0) {
      double total = g_pos_sum[ch] + sh_acc;        // L1 cold for this addr; L2-coherent
      long long denom = (long long)np + k;
      double loss = (denom > 0) ? (total / (double)denom) : 0.0;
      loss_total += loss;
    }
    __syncthreads();
  }

  if (tid == 0) {
    dout[0] = (float)loss_total;
    g_done2 = 0u;                                   // reset for next replay
  }
}

// ---------------- launcher: 2 graph nodes only ----------------
extern "C" void kernel_launch(void* const* d_in, const int* in_sizes, int n_in,
                              void* d_out, int out_size) {
  const float* outp = (const float*)d_in[0];
  const float* cm   = (const float*)d_in[1];
  const float* am   = (const float*)d_in[2];
  const float* cw   = (const float*)d_in[3];
  const float* aw   = (const float*)d_in[4];
  float* o = (float*)d_out;
  int N = in_sizes[1];                              // B*H*W = 16,777,216

  int nsamp = N / 64;
  k_sample<<<(nsamp + 1023) / 1024, 1024>>>(outp, cm, am, N);
  k_main<<<GRID2, BLK2>>>(outp, cm, am, cw, aw, o, N);
}